// round 3
// baseline (speedup 1.0000x reference)
#include <cuda_runtime.h>
#include <cstdint>

// TurboQuantValue: per-row (128 elems) 4-bit min/max quantize + dequantize.
// out[i] = clip(rint((x[i]-vmin)/(vscale+1e-10)),0,15)*vscale + vmin
// vscale = (vmax-vmin)/(15+1e-10)
//
// One warp handles FOUR rows (4x front-batched LDG.128 per thread -> MLP=4).
// min/max via REDUX.SYNC on order-preserving uint keys.
// Streaming cache hints (.cs) on both load and store — one-pass 512MB stream.

#define WARPS_PER_BLOCK 8
#define ROWS_PER_WARP 4
#define THREADS (WARPS_PER_BLOCK * 32)

// Order-preserving float<->uint key: key ascending <=> float ascending.
__device__ __forceinline__ unsigned f2key(float f) {
    unsigned u = __float_as_uint(f);
    return u ^ ((unsigned)((int)u >> 31) | 0x80000000u);
}
__device__ __forceinline__ float key2f(unsigned k) {
    unsigned u = (k & 0x80000000u) ? (k ^ 0x80000000u) : ~k;
    return __uint_as_float(u);
}

__device__ __forceinline__ float4 quant_row(float4 a) {
    float mn = fminf(fminf(a.x, a.y), fminf(a.z, a.w));
    float mx = fmaxf(fmaxf(a.x, a.y), fmaxf(a.z, a.w));

    unsigned kmn = __reduce_min_sync(0xFFFFFFFFu, f2key(mn));
    unsigned kmx = __reduce_max_sync(0xFFFFFFFFu, f2key(mx));
    mn = key2f(kmn);
    mx = key2f(kmx);

    float vscale = (mx - mn) / (15.0f + 1e-10f);
    float inv    = 1.0f / (vscale + 1e-10f);
    float nb     = -mn * inv;

    float4 r;
    float q;
    q = fminf(fmaxf(rintf(fmaf(a.x, inv, nb)), 0.0f), 15.0f);
    r.x = fmaf(q, vscale, mn);
    q = fminf(fmaxf(rintf(fmaf(a.y, inv, nb)), 0.0f), 15.0f);
    r.y = fmaf(q, vscale, mn);
    q = fminf(fmaxf(rintf(fmaf(a.z, inv, nb)), 0.0f), 15.0f);
    r.z = fmaf(q, vscale, mn);
    q = fminf(fmaxf(rintf(fmaf(a.w, inv, nb)), 0.0f), 15.0f);
    r.w = fmaf(q, vscale, mn);
    return r;
}

__global__ __launch_bounds__(THREADS)
void turboquant_kernel(const float4* __restrict__ in,
                       float4* __restrict__ out,
                       int n_rows)
{
    int warp_in_block = threadIdx.x >> 5;
    int lane = threadIdx.x & 31;
    int row0 = (blockIdx.x * WARPS_PER_BLOCK + warp_in_block) * ROWS_PER_WARP;
    if (row0 >= n_rows) return;

    size_t idx0 = (size_t)row0 * 32 + lane;   // 32 float4 per row

    // Front-batch 4 independent streaming loads (MLP_p1 = 4)
    float4 a = __ldcs(&in[idx0]);
    float4 b = __ldcs(&in[idx0 + 32]);
    float4 c = __ldcs(&in[idx0 + 64]);
    float4 d = __ldcs(&in[idx0 + 96]);

    float4 ra = quant_row(a);
    float4 rb = quant_row(b);
    float4 rc = quant_row(c);
    float4 rd = quant_row(d);

    __stcs(&out[idx0],      ra);
    __stcs(&out[idx0 + 32], rb);
    __stcs(&out[idx0 + 64], rc);
    __stcs(&out[idx0 + 96], rd);
}

extern "C" void kernel_launch(void* const* d_in, const int* in_sizes, int n_in,
                              void* d_out, int out_size)
{
    const float4* x = (const float4*)d_in[0];
    float4* out = (float4*)d_out;

    int n_elems = in_sizes[0];          // 67,108,864
    int n_rows = n_elems / 128;         // 524,288

    int rows_per_block = WARPS_PER_BLOCK * ROWS_PER_WARP;
    int blocks = (n_rows + rows_per_block - 1) / rows_per_block;
    turboquant_kernel<<<blocks, THREADS>>>(x, out, n_rows);
}